// round 12
// baseline (speedup 1.0000x reference)
#include <cuda_runtime.h>
#include <cuda_fp16.h>
#include <math.h>
#include <stdint.h>

// ---------------------------------------------------------------------------
// PEER-LoRA on GB300 via mma.sync f16 (baseline PTX; tcgen05 unavailable on
// compute_103 target). Static smem only; kernel_launch = launches only.
//
//  1) M = fold(keys, Wq)  [2048,1024] (fp32 SIMT)
//  2) f16 split: A = hi+lo. sim: B split too (3 chains, exact argmax).
//     hidden/out: B = hi only (2 chains, err ~1e-4).
//  3) sim = x @ M^T : per-row argmax fused in epilogue (64-col tiles)
//  4) hidden GEMM writes pre-activation as split f16 hi/lo; expert_in
//     reconstructs, adds LoRA, gelu, rewrites hi/lo; out GEMM consumes hi/lo.
//  5) expert tables pre-converted to f16: gather traffic halved.
// ---------------------------------------------------------------------------

#define TOKENS 8192
#define DIM 1024
#define DINNER 2048
#define HEADS 8
#define NKEYS 128
#define DKEY 512
#define NEXP 16384

// ------------------------------ scratch ------------------------------------
__device__ float g_M[2048 * 1024];
__device__ __half g_x_hi[TOKENS * DIM],   g_x_lo[TOKENS * DIM];
__device__ __half g_M_hi[2048 * DIM],     g_M_lo[2048 * DIM];
__device__ __half g_Wi_h[DINNER * DIM];
__device__ __half g_Wo_h[DIM * DINNER];
__device__ __half g_h_hi[TOKENS * DINNER], g_h_lo[TOKENS * DINNER];
__device__ __half g_ina_h[(size_t)NEXP * DIM];
__device__ __half g_inb_h[(size_t)NEXP * DINNER];
__device__ __half g_outa_h[(size_t)NEXP * DINNER];
__device__ __half g_outb_h[(size_t)NEXP * DIM];
__device__ float g_pm[TOKENS * 32];
__device__ int   g_pi[TOKENS * 32];
__device__ int   g_idx[TOKENS * HEADS];
__device__ float g_gate[TOKENS * HEADS];

// ------------------------------ PTX helpers --------------------------------
__device__ __forceinline__ uint32_t smem_u32(const void* p) {
    uint32_t a;
    asm("{ .reg .u64 t; cvta.to.shared.u64 t, %1; cvt.u32.u64 %0, t; }"
        : "=r"(a) : "l"(p));
    return a;
}
__device__ __forceinline__ void cp16(uint32_t dst, const void* src) {
    asm volatile("cp.async.cg.shared.global [%0], [%1], 16;" :: "r"(dst), "l"(src));
}
#define CP_COMMIT() asm volatile("cp.async.commit_group;" ::: "memory")
#define CP_WAIT(n)  asm volatile("cp.async.wait_group %0;" :: "n"(n) : "memory")

__device__ __forceinline__ void ldm4(uint32_t* r, uint32_t addr) {
    asm volatile("ldmatrix.sync.aligned.m8n8.x4.shared.b16 {%0,%1,%2,%3}, [%4];"
                 : "=r"(r[0]), "=r"(r[1]), "=r"(r[2]), "=r"(r[3]) : "r"(addr));
}
__device__ __forceinline__ void mma_f16(float* d, const uint32_t* a, const uint32_t* b) {
    asm volatile(
        "mma.sync.aligned.m16n8k16.row.col.f32.f16.f16.f32 "
        "{%0,%1,%2,%3}, {%4,%5,%6,%7}, {%8,%9}, {%0,%1,%2,%3};"
        : "+f"(d[0]), "+f"(d[1]), "+f"(d[2]), "+f"(d[3])
        : "r"(a[0]), "r"(a[1]), "r"(a[2]), "r"(a[3]), "r"(b[0]), "r"(b[1]));
}

__device__ __forceinline__ uint32_t lm_addr64(uint32_t tile, int r0, int k0, int lane) {
    int row = r0 + (lane & 15);
    int kk  = k0 + (lane >> 4) * 8;
    uint32_t off = (uint32_t)(row * 64 + kk * 2);
    return tile + (off ^ ((off >> 3) & 0x30));
}

// --------------------- sim GEMM: 128x64 tile, 3 chains ---------------------
#define SMH3 24576

__global__ void __launch_bounds__(256) gemm_sim_tc()
{
    const int K = DIM, nchunk = 32;
    __shared__ __align__(128) char sm_raw[2 * SMH3];
    const uint32_t sm = smem_u32(sm_raw);
    const int tid  = threadIdx.x;
    const int lane = tid & 31;
    const int wid  = tid >> 5;
    const int wm   = wid >> 2;
    const int wn   = wid & 3;
    const int gid  = lane >> 2;
    const int tig  = lane & 3;
    const int bx = blockIdx.x;
    const int bm = blockIdx.y;

    const __half* srcAh = g_x_hi + (size_t)(bm * 128) * K;
    const __half* srcAl = g_x_lo + (size_t)(bm * 128) * K;
    const __half* srcBh = g_M_hi + (size_t)(bx * 64) * K;
    const __half* srcBl = g_M_lo + (size_t)(bx * 64) * K;

    auto load_stage = [&](int chunk, int buf) {
        const uint32_t base = sm + buf * SMH3;
        const int ch   = tid & 3;
        const int kcol = chunk * 32 + ch * 8;
#pragma unroll
        for (int i = 0; i < 2; i++) {
            int row = (tid + i * 256) >> 2;
            uint32_t off = row * 64 + ch * 16;
            uint32_t swz = off ^ ((off >> 3) & 0x30);
            cp16(base + swz,        srcAh + (size_t)row * K + kcol);
            cp16(base + 8192 + swz, srcAl + (size_t)row * K + kcol);
        }
        {
            int row = tid >> 2;
            uint32_t off = row * 64 + ch * 16;
            uint32_t swz = off ^ ((off >> 3) & 0x30);
            cp16(base + 16384 + swz, srcBh + (size_t)row * K + kcol);
            cp16(base + 20480 + swz, srcBl + (size_t)row * K + kcol);
        }
        CP_COMMIT();
    };

    float acc[4][2][4] = {};
    load_stage(0, 0);

    for (int c = 0; c < nchunk; c++) {
        const int buf = c & 1;
        CP_WAIT(0);
        __syncthreads();
        if (c + 1 < nchunk) load_stage(c + 1, 1 - buf);

        const uint32_t tb = sm + buf * SMH3;
#pragma unroll
        for (int k0 = 0; k0 < 32; k0 += 16) {
            uint32_t bhf[2][2], blf[2][2];
            {
                uint32_t r[4];
                ldm4(r, lm_addr64(tb + 16384, wn * 16, k0, lane));
                bhf[0][0] = r[0]; bhf[1][0] = r[1];
                bhf[0][1] = r[2]; bhf[1][1] = r[3];
                ldm4(r, lm_addr64(tb + 20480, wn * 16, k0, lane));
                blf[0][0] = r[0]; blf[1][0] = r[1];
                blf[0][1] = r[2]; blf[1][1] = r[3];
            }
#pragma unroll
            for (int i = 0; i < 4; i++) {
                uint32_t ah[4], al[4];
                ldm4(ah, lm_addr64(tb,        wm * 64 + i * 16, k0, lane));
                ldm4(al, lm_addr64(tb + 8192, wm * 64 + i * 16, k0, lane));
#pragma unroll
                for (int j = 0; j < 2; j++) {
                    mma_f16(acc[i][j], ah, bhf[j]);
                    mma_f16(acc[i][j], al, bhf[j]);
                    mma_f16(acc[i][j], ah, blf[j]);
                }
            }
        }
    }
    __syncthreads();

    float* smax = (float*)sm_raw;
    int*   sidx = (int*)(sm_raw + 2048);
#pragma unroll
    for (int i = 0; i < 4; i++) {
#pragma unroll
        for (int h2 = 0; h2 < 2; h2++) {
            const int rl = wm * 64 + i * 16 + h2 * 8 + gid;
            float m = -1e30f; int mi = 0;
#pragma unroll
            for (int j = 0; j < 2; j++) {
                const int cl = wn * 16 + j * 8 + tig * 2;
                float v0 = acc[i][j][h2 * 2], v1 = acc[i][j][h2 * 2 + 1];
                if (v0 > m) { m = v0; mi = cl; }
                if (v1 > m) { m = v1; mi = cl + 1; }
            }
#pragma unroll
            for (int d = 1; d <= 2; d <<= 1) {
                float om = __shfl_xor_sync(0xffffffffu, m, d);
                int   oi = __shfl_xor_sync(0xffffffffu, mi, d);
                if (om > m || (om == m && oi < mi)) { m = om; mi = oi; }
            }
            if (tig == 0) { smax[rl * 4 + wn] = m; sidx[rl * 4 + wn] = mi; }
        }
    }
    __syncthreads();
    if (tid < 128) {
        float m = smax[tid * 4]; int mi = sidx[tid * 4];
#pragma unroll
        for (int w = 1; w < 4; w++) {
            float om = smax[tid * 4 + w]; int oi = sidx[tid * 4 + w];
            if (om > m || (om == m && oi < mi)) { m = om; mi = oi; }
        }
        g_pm[(size_t)(bm * 128 + tid) * 32 + bx] = m;
        g_pi[(size_t)(bm * 128 + tid) * 32 + bx] = mi + (bx & 1) * 64;
    }
}

// ------------------- 2-chain GEMM: 128x128 tile, 48KB smem -----------------
#define SMH2 24576

template <int MODE>
__device__ __forceinline__ void gemm_core2(
    const __half* __restrict__ Ahi, const __half* __restrict__ Alo,
    const __half* __restrict__ Bhi,
    float* __restrict__ C, __half* __restrict__ Hh, __half* __restrict__ Hl,
    int K, int nchunk, int ldc)
{
    __shared__ __align__(128) char sm_raw[2 * SMH2];
    const uint32_t sm = smem_u32(sm_raw);
    const int tid  = threadIdx.x;
    const int lane = tid & 31;
    const int wid  = tid >> 5;
    const int wm   = wid >> 2;
    const int wn   = wid & 3;
    const int gid  = lane >> 2;
    const int tig  = lane & 3;
    const int bx = blockIdx.x;
    const int bm = blockIdx.y;

    const __half* srcAh = Ahi + (size_t)(bm * 128) * K;
    const __half* srcAl = Alo + (size_t)(bm * 128) * K;
    const __half* srcBh = Bhi + (size_t)(bx * 128) * K;

    auto load_stage = [&](int chunk, int buf) {
        const uint32_t base = sm + buf * SMH2;
        const int ch   = tid & 3;
        const int kcol = chunk * 32 + ch * 8;
#pragma unroll
        for (int i = 0; i < 2; i++) {
            int row = (tid + i * 256) >> 2;
            uint32_t off = row * 64 + ch * 16;
            uint32_t swz = off ^ ((off >> 3) & 0x30);
            cp16(base + swz,         srcAh + (size_t)row * K + kcol);
            cp16(base + 8192 + swz,  srcAl + (size_t)row * K + kcol);
            cp16(base + 16384 + swz, srcBh + (size_t)row * K + kcol);
        }
        CP_COMMIT();
    };

    float acc[4][4][4] = {};
    load_stage(0, 0);

    for (int c = 0; c < nchunk; c++) {
        const int buf = c & 1;
        CP_WAIT(0);
        __syncthreads();
        if (c + 1 < nchunk) load_stage(c + 1, 1 - buf);

        const uint32_t tb = sm + buf * SMH2;
#pragma unroll
        for (int k0 = 0; k0 < 32; k0 += 16) {
            uint32_t bf[4][2];
#pragma unroll
            for (int j2 = 0; j2 < 2; j2++) {
                uint32_t r[4];
                ldm4(r, lm_addr64(tb + 16384, wn * 32 + j2 * 16, k0, lane));
                bf[2 * j2][0] = r[0]; bf[2 * j2 + 1][0] = r[1];
                bf[2 * j2][1] = r[2]; bf[2 * j2 + 1][1] = r[3];
            }
#pragma unroll
            for (int i = 0; i < 4; i++) {
                uint32_t ah[4], al[4];
                ldm4(ah, lm_addr64(tb,        wm * 64 + i * 16, k0, lane));
                ldm4(al, lm_addr64(tb + 8192, wm * 64 + i * 16, k0, lane));
#pragma unroll
                for (int j = 0; j < 4; j++) {
                    mma_f16(acc[i][j], ah, bf[j]);
                    mma_f16(acc[i][j], al, bf[j]);
                }
            }
        }
    }

#pragma unroll
    for (int i = 0; i < 4; i++) {
        const int r0 = bm * 128 + wm * 64 + i * 16 + gid;
#pragma unroll
        for (int j = 0; j < 4; j++) {
            const int cc = bx * 128 + wn * 32 + j * 8 + tig * 2;
            if (MODE == 0) {
                *(float2*)(C + (size_t)r0 * ldc + cc) =
                    make_float2(acc[i][j][0], acc[i][j][1]);
                *(float2*)(C + (size_t)(r0 + 8) * ldc + cc) =
                    make_float2(acc[i][j][2], acc[i][j][3]);
            } else {
#pragma unroll
                for (int h2 = 0; h2 < 2; h2++) {
                    float v0 = acc[i][j][h2 * 2], v1 = acc[i][j][h2 * 2 + 1];
                    __half a0 = __float2half_rn(v0), a1 = __float2half_rn(v1);
                    __half b0 = __float2half_rn(v0 - __half2float(a0));
                    __half b1 = __float2half_rn(v1 - __half2float(a1));
                    size_t e = ((size_t)(r0 + h2 * 8) * ldc + cc) >> 1;
                    ((__half2*)Hh)[e] = __halves2half2(a0, a1);
                    ((__half2*)Hl)[e] = __halves2half2(b0, b1);
                }
            }
        }
    }
}

__global__ void __launch_bounds__(256) gemm_hidden_tc() {
    gemm_core2<2>(g_x_hi, g_x_lo, g_Wi_h, (float*)0, g_h_hi, g_h_lo, DIM, 32, DINNER);
}
__global__ void __launch_bounds__(256) gemm_out_tc(float* __restrict__ C) {
    gemm_core2<0>(g_h_hi, g_h_lo, g_Wo_h, C, (__half*)0, (__half*)0, DINNER, 64, DIM);
}

// ------------------------------ f16 converts -------------------------------
__device__ __forceinline__ void cvt_split(const float* __restrict__ src,
                                          __half* __restrict__ hi,
                                          __half* __restrict__ lo, int n4)
{
    int i = blockIdx.x * blockDim.x + threadIdx.x;
    if (i >= n4) return;
    float4 v = ((const float4*)src)[i];
    __half hx = __float2half_rn(v.x), hy = __float2half_rn(v.y);
    __half hz = __float2half_rn(v.z), hw = __float2half_rn(v.w);
    ((__half2*)hi)[2 * i]     = __halves2half2(hx, hy);
    ((__half2*)hi)[2 * i + 1] = __halves2half2(hz, hw);
    ((__half2*)lo)[2 * i]     = __halves2half2(__float2half_rn(v.x - __half2float(hx)),
                                               __float2half_rn(v.y - __half2float(hy)));
    ((__half2*)lo)[2 * i + 1] = __halves2half2(__float2half_rn(v.z - __half2float(hz)),
                                               __float2half_rn(v.w - __half2float(hw)));
}
__device__ __forceinline__ void cvt_one(const float* __restrict__ src,
                                        __half* __restrict__ hi, int n4)
{
    int i = blockIdx.x * blockDim.x + threadIdx.x;
    if (i >= n4) return;
    float4 v = ((const float4*)src)[i];
    ((__half2*)hi)[2 * i]     = __floats2half2_rn(v.x, v.y);
    ((__half2*)hi)[2 * i + 1] = __floats2half2_rn(v.z, v.w);
}
__global__ void cvt_x_k(const float* __restrict__ s)  { cvt_split(s, g_x_hi, g_x_lo, TOKENS * DIM / 4); }
__global__ void cvt_M_k()                             { cvt_split(g_M, g_M_hi, g_M_lo, 2048 * DIM / 4); }
__global__ void cvt_Wi_k(const float* __restrict__ s) { cvt_one(s, g_Wi_h, DINNER * DIM / 4); }
__global__ void cvt_Wo_k(const float* __restrict__ s) { cvt_one(s, g_Wo_h, DIM * DINNER / 4); }
__global__ void cvt_ina_k(const float* __restrict__ s)  { cvt_one(s, g_ina_h,  NEXP * DIM / 4); }
__global__ void cvt_inb_k(const float* __restrict__ s)  { cvt_one(s, g_inb_h,  NEXP * DINNER / 4); }
__global__ void cvt_outa_k(const float* __restrict__ s) { cvt_one(s, g_outa_h, NEXP * DINNER / 4); }
__global__ void cvt_outb_k(const float* __restrict__ s) { cvt_one(s, g_outb_h, NEXP * DIM / 4); }

// ------------------------------ M build (fp32 SIMT, 128x64) ----------------
__global__ void __launch_bounds__(256, 2) gemm_nn_mbuild(
    const float* __restrict__ keys, const float* __restrict__ Wq)
{
    const int z = blockIdx.z, p = z >> 3, h = z & 7;
    const float* A = keys + (size_t)h * (NKEYS * 2 * DKEY) + (size_t)p * DKEY;
    const float* B = Wq + (size_t)(p * 8 + h) * DKEY * DIM;
    float* C = g_M + (size_t)(p * 1024 + h * 128) * DIM;

    __shared__ float As[16][128];
    __shared__ float Bs[16][64];
    const int t = threadIdx.x;
    const int tx = t & 15, ty = t >> 4;
    const int rowA = t >> 1, lkA = (t & 1) << 3;
    const int krB = t >> 4, ncB = (t & 15) << 2;
    const int bx = blockIdx.x;
    float acc[8][4] = {};

    for (int k0 = 0; k0 < DKEY; k0 += 16) {
        float4 a0 = *(const float4*)(A + (size_t)rowA * 1024 + k0 + lkA);
        float4 a1 = *(const float4*)(A + (size_t)rowA * 1024 + k0 + lkA + 4);
        float4 b0 = *(const float4*)(B + (size_t)(k0 + krB) * DIM + bx * 64 + ncB);
        __syncthreads();
        As[lkA + 0][rowA] = a0.x; As[lkA + 1][rowA] = a0.y;
        As[lkA + 2][rowA] = a0.z; As[lkA + 3][rowA] = a0.w;
        As[lkA + 4][rowA] = a1.x; As[lkA + 5][rowA] = a1.y;
        As[lkA + 6][rowA] = a1.z; As[lkA + 7][rowA] = a1.w;
        *(float4*)&Bs[krB][ncB] = b0;
        __syncthreads();
#pragma unroll
        for (int kk = 0; kk < 16; kk++) {
            float4 av0 = *(const float4*)&As[kk][ty * 8];
            float4 av1 = *(const float4*)&As[kk][ty * 8 + 4];
            float4 bv = *(const float4*)&Bs[kk][tx * 4];
            float ar[8] = {av0.x, av0.y, av0.z, av0.w, av1.x, av1.y, av1.z, av1.w};
            float br[4] = {bv.x, bv.y, bv.z, bv.w};
#pragma unroll
            for (int i = 0; i < 8; i++)
#pragma unroll
                for (int j = 0; j < 4; j++) acc[i][j] += ar[i] * br[j];
        }
    }
    float* Cb = C + (size_t)(ty * 8) * DIM + bx * 64 + tx * 4;
#pragma unroll
    for (int i = 0; i < 8; i++)
        *(float4*)(Cb + (size_t)i * DIM) =
            make_float4(acc[i][0], acc[i][1], acc[i][2], acc[i][3]);
}

// ------------------------------ argmax combine -----------------------------
__global__ void combine_k()
{
    int i = blockIdx.x * blockDim.x + threadIdx.x;
    if (i >= TOKENS * HEADS) return;
    int t = i >> 3, h = i & 7;
    const float* pm = g_pm + (size_t)t * 32;
    const int*   pi = g_pi + (size_t)t * 32;

    float m0 = pm[2 * h];     int i0 = pi[2 * h];
    {   float om = pm[2 * h + 1]; int oi = pi[2 * h + 1];
        if (om > m0 || (om == m0 && oi < i0)) { m0 = om; i0 = oi; } }
    float m1 = pm[16 + 2 * h]; int i1 = pi[16 + 2 * h];
    {   float om = pm[16 + 2 * h + 1]; int oi = pi[16 + 2 * h + 1];
        if (om > m1 || (om == m1 && oi < i1)) { m1 = om; i1 = oi; } }

    g_idx[i] = i0 * NKEYS + i1;
    float s = m0 + m1;
    g_gate[i] = s > 0.f ? s : 0.f;
}

// ------------------------------ expert kernels -----------------------------
__device__ __forceinline__ float gelu_exact(float v)
{
    return 0.5f * v * (1.0f + erff(v * 0.7071067811865476f));
}
__device__ __forceinline__ float4 h4_to_f4(uint2 u)
{
    float2 f0 = __half22float2(*(__half2*)&u.x);
    float2 f1 = __half22float2(*(__half2*)&u.y);
    return make_float4(f0.x, f0.y, f1.x, f1.y);
}

__global__ void __launch_bounds__(256) expert_in_k(
    const float* __restrict__ x)
{
    const int t = blockIdx.x;
    const int tid = threadIdx.x;
    __shared__ int s_idx[8];
    __shared__ float s_g[8];
    __shared__ float s_red[8][9];
    __shared__ float s_lin[8];

    if (tid < 8) { s_idx[tid] = g_idx[t * 8 + tid]; s_g[tid] = g_gate[t * 8 + tid]; }
    __syncthreads();

    const float4* x4 = (const float4*)(x + (size_t)t * DIM);
    float4 xv = x4[tid];
    float acc[8];
#pragma unroll
    for (int e = 0; e < 8; e++) {
        const uint2* a2 = (const uint2*)(g_ina_h + (size_t)s_idx[e] * DIM);
        float4 av = h4_to_f4(a2[tid]);
        acc[e] = xv.x * av.x + xv.y * av.y + xv.z * av.z + xv.w * av.w;
    }
    const int lane = tid & 31, wid = tid >> 5;
#pragma unroll
    for (int e = 0; e < 8; e++) {
        float v = acc[e];
#pragma unroll
        for (int off = 16; off; off >>= 1) v += __shfl_down_sync(0xffffffffu, v, off);
        if (lane == 0) s_red[e][wid] = v;
    }
    __syncthreads();
    if (tid < 8) {
        float s = 0.f;
#pragma unroll
        for (int w = 0; w < 8; w++) s += s_red[tid][w];
        s_lin[tid] = s * s_g[tid];
    }
    __syncthreads();

    __half2* hh2 = (__half2*)g_h_hi + (size_t)t * (DINNER / 2);
    __half2* hl2 = (__half2*)g_h_lo + (size_t)t * (DINNER / 2);
#pragma unroll
    for (int r = 0; r < 2; r++) {
        int j = tid + (r << 8);
        float2 a0 = __half22float2(hh2[2 * j]);
        float2 a1 = __half22float2(hh2[2 * j + 1]);
        float2 b0 = __half22float2(hl2[2 * j]);
        float2 b1 = __half22float2(hl2[2 * j + 1]);
        float4 v = make_float4(a0.x + b0.x, a0.y + b0.y, a1.x + b1.x, a1.y + b1.y);
#pragma unroll
        for (int e = 0; e < 8; e++) {
            const uint2* b2 = (const uint2*)(g_inb_h + (size_t)s_idx[e] * DINNER);
            float4 bv = h4_to_f4(b2[j]);
            float l = s_lin[e];
            v.x += l * bv.x; v.y += l * bv.y; v.z += l * bv.z; v.w += l * bv.w;
        }
        v.x = gelu_exact(v.x); v.y = gelu_exact(v.y);
        v.z = gelu_exact(v.z); v.w = gelu_exact(v.w);
        __half hx = __float2half_rn(v.x), hy = __float2half_rn(v.y);
        __half hz = __float2half_rn(v.z), hw = __float2half_rn(v.w);
        hh2[2 * j]     = __halves2half2(hx, hy);
        hh2[2 * j + 1] = __halves2half2(hz, hw);
        hl2[2 * j]     = __halves2half2(__float2half_rn(v.x - __half2float(hx)),
                                        __float2half_rn(v.y - __half2float(hy)));
        hl2[2 * j + 1] = __halves2half2(__float2half_rn(v.z - __half2float(hz)),
                                        __float2half_rn(v.w - __half2float(hw)));
    }
}

__global__ void __launch_bounds__(256) expert_out_k(float* __restrict__ out)
{
    const int t = blockIdx.x;
    const int tid = threadIdx.x;
    __shared__ int s_idx[8];
    __shared__ float s_g[8];
    __shared__ float s_red[8][9];
    __shared__ float s_l[8];

    if (tid < 8) { s_idx[tid] = g_idx[t * 8 + tid]; s_g[tid] = g_gate[t * 8 + tid]; }
    __syncthreads();

    const __half2* hh2 = (const __half2*)g_h_hi + (size_t)t * (DINNER / 2);
    const __half2* hl2 = (const __half2*)g_h_lo + (size_t)t * (DINNER / 2);
    float acc[8] = {};
#pragma unroll
    for (int r = 0; r < 2; r++) {
        int j = tid + (r << 8);
        float2 a0 = __half22float2(hh2[2 * j]);
        float2 a1 = __half22float2(hh2[2 * j + 1]);
        float2 b0 = __half22float2(hl2[2 * j]);
        float2 b1 = __half22float2(hl2[2 * j + 1]);
        float4 hv = make_float4(a0.x + b0.x, a0.y + b0.y, a1.x + b1.x, a1.y + b1.y);
#pragma unroll
        for (int e = 0; e < 8; e++) {
            const uint2* a2 = (const uint2*)(g_outa_h + (size_t)s_idx[e] * DINNER);
            float4 av = h4_to_f4(a2[j]);
            acc[e] += hv.x * av.x + hv.y * av.y + hv.z * av.z + hv.w * av.w;
        }
    }
    const int lane = tid & 31, wid = tid >> 5;
#pragma unroll
    for (int e = 0; e < 8; e++) {
        float v = acc[e];
#pragma unroll
        for (int off = 16; off; off >>= 1) v += __shfl_down_sync(0xffffffffu, v, off);
        if (lane == 0) s_red[e][wid] = v;
    }
    __syncthreads();
    if (tid < 8) {
        float s = 0.f;
#pragma unroll
        for (int w = 0; w < 8; w++) s += s_red[tid][w];
        s_l[tid] = s * s_g[tid];
    }
    __syncthreads();

    float4* o4 = (float4*)(out + (size_t)t * DIM);
    float4 v = o4[tid];
#pragma unroll
    for (int e = 0; e < 8; e++) {
        const uint2* b2 = (const uint2*)(g_outb_h + (size_t)s_idx[e] * DIM);
        float4 bv = h4_to_f4(b2[tid]);
        float l = s_l[e];
        v.x += l * bv.x; v.y += l * bv.y; v.z += l * bv.z; v.w += l * bv.w;
    }
    o4[tid] = v;
}

// ---------------------------------------------------------------------------
extern "C" void kernel_launch(void* const* d_in, const int* in_sizes, int n_in,
                              void* d_out, int out_size)
{
    const float* x     = (const float*)d_in[0];
    const float* Wq    = (const float*)d_in[1];
    const float* keys  = (const float*)d_in[2];
    const float* W_in  = (const float*)d_in[3];
    const float* W_out = (const float*)d_in[4];
    const float* in_a  = (const float*)d_in[5];
    const float* in_b  = (const float*)d_in[6];
    const float* out_a = (const float*)d_in[7];
    const float* out_b = (const float*)d_in[8];
    float* out = (float*)d_out;

    // (1) cvt_x (2) cvt_Wi (3) mbuild (4) hidden <- profiled launch slot
    cvt_x_k<<<TOKENS * DIM / 4 / 256, 256>>>(x);
    cvt_Wi_k<<<DINNER * DIM / 4 / 256, 256>>>(W_in);
    gemm_nn_mbuild<<<dim3(16, 1, 16), 256>>>(keys, Wq);
    gemm_hidden_tc<<<dim3(16, TOKENS / 128), 256>>>();

    // retrieval
    cvt_M_k<<<2048 * DIM / 4 / 256, 256>>>();
    gemm_sim_tc<<<dim3(32, TOKENS / 128), 256>>>();
    combine_k<<<TOKENS * HEADS / 256, 256>>>();

    // expert tables -> f16
    cvt_ina_k<<<NEXP * DIM / 4 / 256, 256>>>(in_a);
    cvt_inb_k<<<NEXP * DINNER / 4 / 256, 256>>>(in_b);

    // expert_in (+gelu, rewrites h hi/lo)
    expert_in_k<<<TOKENS, 256>>>(x);

    // out = h @ W_out^T ; + experts
    cvt_Wo_k<<<DIM * DINNER / 4 / 256, 256>>>(W_out);
    cvt_outa_k<<<NEXP * DINNER / 4 / 256, 256>>>(out_a);
    cvt_outb_k<<<NEXP * DIM / 4 / 256, 256>>>(out_b);
    gemm_out_tc<<<dim3(8, TOKENS / 128), 256>>>(out);
    expert_out_k<<<TOKENS, 256>>>(out);
}

// round 13
// speedup vs baseline: 1.0395x; 1.0395x over previous
#include <cuda_runtime.h>
#include <cuda_fp16.h>
#include <math.h>
#include <stdint.h>

// ---------------------------------------------------------------------------
// PEER-LoRA on GB300 via mma.sync f16 (baseline PTX; tcgen05 unavailable on
// compute_103 target).
//
//  1) mbuild: M = fold(keys, Wq) [2048,1024] fp32 SIMT, epilogue emits
//     split-f16 M_hi/M_lo directly (no fp32 M tensor).
//  2) sim = x @ M^T : 128x128 tile, 3 MMA chains (exact argmax), dynamic smem
//     64KB, per-row argmax fused in epilogue (one tile = one (p,h) group).
//  3) hidden = x @ W_in^T : 2-chain 128x128 (static 48KB), writes split f16.
//     expert_in (fp32 tables) adds LoRA + gelu, rewrites h hi/lo.
//  4) out = h @ W_out^T (2-chain) ; expert_out (fp32 tables) adds LoRA.
// ---------------------------------------------------------------------------

#define TOKENS 8192
#define DIM 1024
#define DINNER 2048
#define HEADS 8
#define NKEYS 128
#define DKEY 512

// ------------------------------ scratch ------------------------------------
__device__ __half g_x_hi[TOKENS * DIM],   g_x_lo[TOKENS * DIM];
__device__ __half g_M_hi[2048 * DIM],     g_M_lo[2048 * DIM];
__device__ __half g_Wi_h[DINNER * DIM];
__device__ __half g_Wo_h[DIM * DINNER];
__device__ __half g_h_hi[TOKENS * DINNER], g_h_lo[TOKENS * DINNER];
__device__ float g_pm[TOKENS * 16];
__device__ int   g_pi[TOKENS * 16];
__device__ int   g_idx[TOKENS * HEADS];
__device__ float g_gate[TOKENS * HEADS];

// ------------------------------ PTX helpers --------------------------------
__device__ __forceinline__ uint32_t smem_u32(const void* p) {
    uint32_t a;
    asm("{ .reg .u64 t; cvta.to.shared.u64 t, %1; cvt.u32.u64 %0, t; }"
        : "=r"(a) : "l"(p));
    return a;
}
__device__ __forceinline__ void cp16(uint32_t dst, const void* src) {
    asm volatile("cp.async.cg.shared.global [%0], [%1], 16;" :: "r"(dst), "l"(src));
}
#define CP_COMMIT() asm volatile("cp.async.commit_group;" ::: "memory")
#define CP_WAIT(n)  asm volatile("cp.async.wait_group %0;" :: "n"(n) : "memory")

__device__ __forceinline__ void ldm4(uint32_t* r, uint32_t addr) {
    asm volatile("ldmatrix.sync.aligned.m8n8.x4.shared.b16 {%0,%1,%2,%3}, [%4];"
                 : "=r"(r[0]), "=r"(r[1]), "=r"(r[2]), "=r"(r[3]) : "r"(addr));
}
__device__ __forceinline__ void mma_f16(float* d, const uint32_t* a, const uint32_t* b) {
    asm volatile(
        "mma.sync.aligned.m16n8k16.row.col.f32.f16.f16.f32 "
        "{%0,%1,%2,%3}, {%4,%5,%6,%7}, {%8,%9}, {%0,%1,%2,%3};"
        : "+f"(d[0]), "+f"(d[1]), "+f"(d[2]), "+f"(d[3])
        : "r"(a[0]), "r"(a[1]), "r"(a[2]), "r"(a[3]), "r"(b[0]), "r"(b[1]));
}

__device__ __forceinline__ uint32_t lm_addr64(uint32_t tile, int r0, int k0, int lane) {
    int row = r0 + (lane & 15);
    int kk  = k0 + (lane >> 4) * 8;
    uint32_t off = (uint32_t)(row * 64 + kk * 2);
    return tile + (off ^ ((off >> 3) & 0x30));
}

// ------------- sim GEMM: 128x128 tile, 3 chains, dynamic smem --------------
// One N-tile (128 cols of M) = one (p,h) key group -> per-row argmax here.
#define SIM_STAGE 32768   // Ah 8K + Al 8K + Bh 8K + Bl 8K
#define SIM_SMEM  (2 * SIM_STAGE)

__global__ void __launch_bounds__(256) gemm_sim_tc()
{
    extern __shared__ __align__(128) char dyn_sm[];
    const int K = DIM, nchunk = 32;
    const uint32_t sm = smem_u32(dyn_sm);
    const int tid  = threadIdx.x;
    const int lane = tid & 31;
    const int wid  = tid >> 5;
    const int wm   = wid >> 2;          // 0..1 -> rows [wm*64, +64)
    const int wn   = wid & 3;           // 0..3 -> cols [wn*32, +32)
    const int gid  = lane >> 2;
    const int tig  = lane & 3;
    const int bx = blockIdx.x;          // N tile (128 cols) = (p,h) group
    const int bm = blockIdx.y;          // M tile (128 rows)

    const __half* srcs[4] = {
        g_x_hi + (size_t)(bm * 128) * K, g_x_lo + (size_t)(bm * 128) * K,
        g_M_hi + (size_t)(bx * 128) * K, g_M_lo + (size_t)(bx * 128) * K };

    auto load_stage = [&](int chunk, int buf) {
        const uint32_t base = sm + buf * SIM_STAGE;
        const int kofs = chunk * 32;
#pragma unroll
        for (int i = 0; i < 8; i++) {
            int c = tid + i * 256;
            int tile = c >> 9;          // 4 tiles x 512 chunks
            int rem = c & 511;
            int row = rem >> 2;
            int ch = rem & 3;
            uint32_t off = row * 64 + ch * 16;
            uint32_t swz = off ^ ((off >> 3) & 0x30);
            cp16(base + tile * 8192 + swz,
                 srcs[tile] + (size_t)row * K + kofs + ch * 8);
        }
        CP_COMMIT();
    };

    float acc[4][4][4] = {};
    load_stage(0, 0);

    for (int c = 0; c < nchunk; c++) {
        const int buf = c & 1;
        CP_WAIT(0);
        __syncthreads();
        if (c + 1 < nchunk) load_stage(c + 1, 1 - buf);

        const uint32_t tb = sm + buf * SIM_STAGE;
#pragma unroll
        for (int k0 = 0; k0 < 32; k0 += 16) {
            uint32_t bh[4][2], bl[4][2];
#pragma unroll
            for (int j2 = 0; j2 < 2; j2++) {
                uint32_t r[4];
                ldm4(r, lm_addr64(tb + 16384, wn * 32 + j2 * 16, k0, lane));
                bh[2 * j2][0] = r[0]; bh[2 * j2 + 1][0] = r[1];
                bh[2 * j2][1] = r[2]; bh[2 * j2 + 1][1] = r[3];
                ldm4(r, lm_addr64(tb + 24576, wn * 32 + j2 * 16, k0, lane));
                bl[2 * j2][0] = r[0]; bl[2 * j2 + 1][0] = r[1];
                bl[2 * j2][1] = r[2]; bl[2 * j2 + 1][1] = r[3];
            }
#pragma unroll
            for (int i = 0; i < 4; i++) {
                uint32_t ah[4], al[4];
                ldm4(ah, lm_addr64(tb,        wm * 64 + i * 16, k0, lane));
                ldm4(al, lm_addr64(tb + 8192, wm * 64 + i * 16, k0, lane));
#pragma unroll
                for (int j = 0; j < 4; j++) {
                    mma_f16(acc[i][j], ah, bh[j]);
                    mma_f16(acc[i][j], al, bh[j]);
                    mma_f16(acc[i][j], ah, bl[j]);
                }
            }
        }
    }
    __syncthreads();

    // per-row argmax over the 128 cols of this tile
    float* smax = (float*)dyn_sm;               // [128][4]
    int*   sidx = (int*)(dyn_sm + 2048);        // [128][4]
#pragma unroll
    for (int i = 0; i < 4; i++) {
#pragma unroll
        for (int h2 = 0; h2 < 2; h2++) {
            const int rl = wm * 64 + i * 16 + h2 * 8 + gid;
            float m = -1e30f; int mi = 0;
#pragma unroll
            for (int j = 0; j < 4; j++) {
                const int cl = wn * 32 + j * 8 + tig * 2;
                float v0 = acc[i][j][h2 * 2], v1 = acc[i][j][h2 * 2 + 1];
                if (v0 > m) { m = v0; mi = cl; }
                if (v1 > m) { m = v1; mi = cl + 1; }
            }
#pragma unroll
            for (int d = 1; d <= 2; d <<= 1) {
                float om = __shfl_xor_sync(0xffffffffu, m, d);
                int   oi = __shfl_xor_sync(0xffffffffu, mi, d);
                if (om > m || (om == m && oi < mi)) { m = om; mi = oi; }
            }
            if (tig == 0) { smax[rl * 4 + wn] = m; sidx[rl * 4 + wn] = mi; }
        }
    }
    __syncthreads();
    if (tid < 128) {
        float m = smax[tid * 4]; int mi = sidx[tid * 4];
#pragma unroll
        for (int w = 1; w < 4; w++) {
            float om = smax[tid * 4 + w]; int oi = sidx[tid * 4 + w];
            if (om > m || (om == m && oi < mi)) { m = om; mi = oi; }
        }
        g_pm[(size_t)(bm * 128 + tid) * 16 + bx] = m;
        g_pi[(size_t)(bm * 128 + tid) * 16 + bx] = mi;
    }
}

// ------------------- 2-chain GEMM: 128x128 tile, 48KB smem -----------------
#define SMH2 24576

template <int MODE>
__device__ __forceinline__ void gemm_core2(
    const __half* __restrict__ Ahi, const __half* __restrict__ Alo,
    const __half* __restrict__ Bhi,
    float* __restrict__ C, __half* __restrict__ Hh, __half* __restrict__ Hl,
    int K, int nchunk, int ldc)
{
    __shared__ __align__(128) char sm_raw[2 * SMH2];
    const uint32_t sm = smem_u32(sm_raw);
    const int tid  = threadIdx.x;
    const int lane = tid & 31;
    const int wid  = tid >> 5;
    const int wm   = wid >> 2;
    const int wn   = wid & 3;
    const int gid  = lane >> 2;
    const int tig  = lane & 3;
    const int bx = blockIdx.x;
    const int bm = blockIdx.y;

    const __half* srcAh = Ahi + (size_t)(bm * 128) * K;
    const __half* srcAl = Alo + (size_t)(bm * 128) * K;
    const __half* srcBh = Bhi + (size_t)(bx * 128) * K;

    auto load_stage = [&](int chunk, int buf) {
        const uint32_t base = sm + buf * SMH2;
        const int ch   = tid & 3;
        const int kcol = chunk * 32 + ch * 8;
#pragma unroll
        for (int i = 0; i < 2; i++) {
            int row = (tid + i * 256) >> 2;
            uint32_t off = row * 64 + ch * 16;
            uint32_t swz = off ^ ((off >> 3) & 0x30);
            cp16(base + swz,         srcAh + (size_t)row * K + kcol);
            cp16(base + 8192 + swz,  srcAl + (size_t)row * K + kcol);
            cp16(base + 16384 + swz, srcBh + (size_t)row * K + kcol);
        }
        CP_COMMIT();
    };

    float acc[4][4][4] = {};
    load_stage(0, 0);

    for (int c = 0; c < nchunk; c++) {
        const int buf = c & 1;
        CP_WAIT(0);
        __syncthreads();
        if (c + 1 < nchunk) load_stage(c + 1, 1 - buf);

        const uint32_t tb = sm + buf * SMH2;
#pragma unroll
        for (int k0 = 0; k0 < 32; k0 += 16) {
            uint32_t bf[4][2];
#pragma unroll
            for (int j2 = 0; j2 < 2; j2++) {
                uint32_t r[4];
                ldm4(r, lm_addr64(tb + 16384, wn * 32 + j2 * 16, k0, lane));
                bf[2 * j2][0] = r[0]; bf[2 * j2 + 1][0] = r[1];
                bf[2 * j2][1] = r[2]; bf[2 * j2 + 1][1] = r[3];
            }
#pragma unroll
            for (int i = 0; i < 4; i++) {
                uint32_t ah[4], al[4];
                ldm4(ah, lm_addr64(tb,        wm * 64 + i * 16, k0, lane));
                ldm4(al, lm_addr64(tb + 8192, wm * 64 + i * 16, k0, lane));
#pragma unroll
                for (int j = 0; j < 4; j++) {
                    mma_f16(acc[i][j], ah, bf[j]);
                    mma_f16(acc[i][j], al, bf[j]);
                }
            }
        }
    }

#pragma unroll
    for (int i = 0; i < 4; i++) {
        const int r0 = bm * 128 + wm * 64 + i * 16 + gid;
#pragma unroll
        for (int j = 0; j < 4; j++) {
            const int cc = bx * 128 + wn * 32 + j * 8 + tig * 2;
            if (MODE == 0) {
                *(float2*)(C + (size_t)r0 * ldc + cc) =
                    make_float2(acc[i][j][0], acc[i][j][1]);
                *(float2*)(C + (size_t)(r0 + 8) * ldc + cc) =
                    make_float2(acc[i][j][2], acc[i][j][3]);
            } else {
#pragma unroll
                for (int h2 = 0; h2 < 2; h2++) {
                    float v0 = acc[i][j][h2 * 2], v1 = acc[i][j][h2 * 2 + 1];
                    __half a0 = __float2half_rn(v0), a1 = __float2half_rn(v1);
                    __half b0 = __float2half_rn(v0 - __half2float(a0));
                    __half b1 = __float2half_rn(v1 - __half2float(a1));
                    size_t e = ((size_t)(r0 + h2 * 8) * ldc + cc) >> 1;
                    ((__half2*)Hh)[e] = __halves2half2(a0, a1);
                    ((__half2*)Hl)[e] = __halves2half2(b0, b1);
                }
            }
        }
    }
}

__global__ void __launch_bounds__(256) gemm_hidden_tc() {
    gemm_core2<2>(g_x_hi, g_x_lo, g_Wi_h, (float*)0, g_h_hi, g_h_lo, DIM, 32, DINNER);
}
__global__ void __launch_bounds__(256) gemm_out_tc(float* __restrict__ C) {
    gemm_core2<0>(g_h_hi, g_h_lo, g_Wo_h, C, (__half*)0, (__half*)0, DINNER, 64, DIM);
}

// ------------------------------ f16 converts -------------------------------
__device__ __forceinline__ void cvt_split(const float* __restrict__ src,
                                          __half* __restrict__ hi,
                                          __half* __restrict__ lo, int n4)
{
    int i = blockIdx.x * blockDim.x + threadIdx.x;
    if (i >= n4) return;
    float4 v = ((const float4*)src)[i];
    __half hx = __float2half_rn(v.x), hy = __float2half_rn(v.y);
    __half hz = __float2half_rn(v.z), hw = __float2half_rn(v.w);
    ((__half2*)hi)[2 * i]     = __halves2half2(hx, hy);
    ((__half2*)hi)[2 * i + 1] = __halves2half2(hz, hw);
    ((__half2*)lo)[2 * i]     = __halves2half2(__float2half_rn(v.x - __half2float(hx)),
                                               __float2half_rn(v.y - __half2float(hy)));
    ((__half2*)lo)[2 * i + 1] = __halves2half2(__float2half_rn(v.z - __half2float(hz)),
                                               __float2half_rn(v.w - __half2float(hw)));
}
__device__ __forceinline__ void cvt_one(const float* __restrict__ src,
                                        __half* __restrict__ hi, int n4)
{
    int i = blockIdx.x * blockDim.x + threadIdx.x;
    if (i >= n4) return;
    float4 v = ((const float4*)src)[i];
    ((__half2*)hi)[2 * i]     = __floats2half2_rn(v.x, v.y);
    ((__half2*)hi)[2 * i + 1] = __floats2half2_rn(v.z, v.w);
}
__global__ void cvt_x_k(const float* __restrict__ s)  { cvt_split(s, g_x_hi, g_x_lo, TOKENS * DIM / 4); }
__global__ void cvt_Wi_k(const float* __restrict__ s) { cvt_one(s, g_Wi_h, DINNER * DIM / 4); }
__global__ void cvt_Wo_k(const float* __restrict__ s) { cvt_one(s, g_Wo_h, DIM * DINNER / 4); }

// --------------- M build (fp32 SIMT, 128x64, emits hi/lo) ------------------
__global__ void __launch_bounds__(256, 2) gemm_nn_mbuild(
    const float* __restrict__ keys, const float* __restrict__ Wq)
{
    const int z = blockIdx.z, p = z >> 3, h = z & 7;
    const float* A = keys + (size_t)h * (NKEYS * 2 * DKEY) + (size_t)p * DKEY;
    const float* B = Wq + (size_t)(p * 8 + h) * DKEY * DIM;
    const size_t crow0 = (size_t)(p * 1024 + h * 128);

    __shared__ float As[16][128];
    __shared__ float Bs[16][64];
    const int t = threadIdx.x;
    const int tx = t & 15, ty = t >> 4;
    const int rowA = t >> 1, lkA = (t & 1) << 3;
    const int krB = t >> 4, ncB = (t & 15) << 2;
    const int bx = blockIdx.x;
    float acc[8][4] = {};

    for (int k0 = 0; k0 < DKEY; k0 += 16) {
        float4 a0 = *(const float4*)(A + (size_t)rowA * 1024 + k0 + lkA);
        float4 a1 = *(const float4*)(A + (size_t)rowA * 1024 + k0 + lkA + 4);
        float4 b0 = *(const float4*)(B + (size_t)(k0 + krB) * DIM + bx * 64 + ncB);
        __syncthreads();
        As[lkA + 0][rowA] = a0.x; As[lkA + 1][rowA] = a0.y;
        As[lkA + 2][rowA] = a0.z; As[lkA + 3][rowA] = a0.w;
        As[lkA + 4][rowA] = a1.x; As[lkA + 5][rowA] = a1.y;
        As[lkA + 6][rowA] = a1.z; As[lkA + 7][rowA] = a1.w;
        *(float4*)&Bs[krB][ncB] = b0;
        __syncthreads();
#pragma unroll
        for (int kk = 0; kk < 16; kk++) {
            float4 av0 = *(const float4*)&As[kk][ty * 8];
            float4 av1 = *(const float4*)&As[kk][ty * 8 + 4];
            float4 bv = *(const float4*)&Bs[kk][tx * 4];
            float ar[8] = {av0.x, av0.y, av0.z, av0.w, av1.x, av1.y, av1.z, av1.w};
            float br[4] = {bv.x, bv.y, bv.z, bv.w};
#pragma unroll
            for (int i = 0; i < 8; i++)
#pragma unroll
                for (int j = 0; j < 4; j++) acc[i][j] += ar[i] * br[j];
        }
    }
#pragma unroll
    for (int i = 0; i < 8; i++) {
        size_t off = (crow0 + ty * 8 + i) * DIM + bx * 64 + tx * 4;
        __half h0 = __float2half_rn(acc[i][0]);
        __half h1 = __float2half_rn(acc[i][1]);
        __half h2 = __float2half_rn(acc[i][2]);
        __half h3 = __float2half_rn(acc[i][3]);
        ((__half2*)(g_M_hi + off))[0] = __halves2half2(h0, h1);
        ((__half2*)(g_M_hi + off))[1] = __halves2half2(h2, h3);
        ((__half2*)(g_M_lo + off))[0] = __halves2half2(
            __float2half_rn(acc[i][0] - __half2float(h0)),
            __float2half_rn(acc[i][1] - __half2float(h1)));
        ((__half2*)(g_M_lo + off))[1] = __halves2half2(
            __float2half_rn(acc[i][2] - __half2float(h2)),
            __float2half_rn(acc[i][3] - __half2float(h3)));
    }
}

// ------------------------------ argmax combine -----------------------------
__global__ void combine_k()
{
    int i = blockIdx.x * blockDim.x + threadIdx.x;   // t*8 + h
    if (i >= TOKENS * HEADS) return;
    int t = i >> 3, h = i & 7;
    float m0 = g_pm[(size_t)t * 16 + h];     int i0 = g_pi[(size_t)t * 16 + h];
    float m1 = g_pm[(size_t)t * 16 + 8 + h]; int i1 = g_pi[(size_t)t * 16 + 8 + h];
    g_idx[i] = i0 * NKEYS + i1;
    float s = m0 + m1;
    g_gate[i] = s > 0.f ? s : 0.f;
}

// ------------------------------ expert kernels -----------------------------
__device__ __forceinline__ float gelu_exact(float v)
{
    return 0.5f * v * (1.0f + erff(v * 0.7071067811865476f));
}

__global__ void __launch_bounds__(256) expert_in_k(
    const float* __restrict__ x, const float* __restrict__ in_a,
    const float* __restrict__ in_b)
{
    const int t = blockIdx.x;
    const int tid = threadIdx.x;
    __shared__ int s_idx[8];
    __shared__ float s_g[8];
    __shared__ float s_red[8][9];
    __shared__ float s_lin[8];

    if (tid < 8) { s_idx[tid] = g_idx[t * 8 + tid]; s_g[tid] = g_gate[t * 8 + tid]; }
    __syncthreads();

    const float4* x4 = (const float4*)(x + (size_t)t * DIM);
    float4 xv = x4[tid];
    float acc[8];
#pragma unroll
    for (int e = 0; e < 8; e++) {
        const float4* a4 = (const float4*)(in_a + (size_t)s_idx[e] * DIM);
        float4 av = a4[tid];
        acc[e] = xv.x * av.x + xv.y * av.y + xv.z * av.z + xv.w * av.w;
    }
    const int lane = tid & 31, wid = tid >> 5;
#pragma unroll
    for (int e = 0; e < 8; e++) {
        float v = acc[e];
#pragma unroll
        for (int off = 16; off; off >>= 1) v += __shfl_down_sync(0xffffffffu, v, off);
        if (lane == 0) s_red[e][wid] = v;
    }
    __syncthreads();
    if (tid < 8) {
        float s = 0.f;
#pragma unroll
        for (int w = 0; w < 8; w++) s += s_red[tid][w];
        s_lin[tid] = s * s_g[tid];
    }
    __syncthreads();

    __half2* hh2 = (__half2*)g_h_hi + (size_t)t * (DINNER / 2);
    __half2* hl2 = (__half2*)g_h_lo + (size_t)t * (DINNER / 2);
#pragma unroll
    for (int r = 0; r < 2; r++) {
        int j = tid + (r << 8);
        float2 a0 = __half22float2(hh2[2 * j]);
        float2 a1 = __half22float2(hh2[2 * j + 1]);
        float2 b0 = __half22float2(hl2[2 * j]);
        float2 b1 = __half22float2(hl2[2 * j + 1]);
        float4 v = make_float4(a0.x + b0.x, a0.y + b0.y, a1.x + b1.x, a1.y + b1.y);
#pragma unroll
        for (int e = 0; e < 8; e++) {
            const float4* b4 = (const float4*)(in_b + (size_t)s_idx[e] * DINNER);
            float4 bv = b4[j];
            float l = s_lin[e];
            v.x += l * bv.x; v.y += l * bv.y; v.z += l * bv.z; v.w += l * bv.w;
        }
        v.x = gelu_exact(v.x); v.y = gelu_exact(v.y);
        v.z = gelu_exact(v.z); v.w = gelu_exact(v.w);
        __half hx = __float2half_rn(v.x), hy = __float2half_rn(v.y);
        __half hz = __float2half_rn(v.z), hw = __float2half_rn(v.w);
        hh2[2 * j]     = __halves2half2(hx, hy);
        hh2[2 * j + 1] = __halves2half2(hz, hw);
        hl2[2 * j]     = __halves2half2(__float2half_rn(v.x - __half2float(hx)),
                                        __float2half_rn(v.y - __half2float(hy)));
        hl2[2 * j + 1] = __halves2half2(__float2half_rn(v.z - __half2float(hz)),
                                        __float2half_rn(v.w - __half2float(hw)));
    }
}

__global__ void __launch_bounds__(256) expert_out_k(
    const float* __restrict__ out_a, const float* __restrict__ out_b,
    float* __restrict__ out)
{
    const int t = blockIdx.x;
    const int tid = threadIdx.x;
    __shared__ int s_idx[8];
    __shared__ float s_g[8];
    __shared__ float s_red[8][9];
    __shared__ float s_l[8];

    if (tid < 8) { s_idx[tid] = g_idx[t * 8 + tid]; s_g[tid] = g_gate[t * 8 + tid]; }
    __syncthreads();

    const __half2* hh2 = (const __half2*)g_h_hi + (size_t)t * (DINNER / 2);
    const __half2* hl2 = (const __half2*)g_h_lo + (size_t)t * (DINNER / 2);
    float acc[8] = {};
#pragma unroll
    for (int r = 0; r < 2; r++) {
        int j = tid + (r << 8);
        float2 a0 = __half22float2(hh2[2 * j]);
        float2 a1 = __half22float2(hh2[2 * j + 1]);
        float2 b0 = __half22float2(hl2[2 * j]);
        float2 b1 = __half22float2(hl2[2 * j + 1]);
        float4 hv = make_float4(a0.x + b0.x, a0.y + b0.y, a1.x + b1.x, a1.y + b1.y);
#pragma unroll
        for (int e = 0; e < 8; e++) {
            const float4* a4 = (const float4*)(out_a + (size_t)s_idx[e] * DINNER);
            float4 av = a4[j];
            acc[e] += hv.x * av.x + hv.y * av.y + hv.z * av.z + hv.w * av.w;
        }
    }
    const int lane = tid & 31, wid = tid >> 5;
#pragma unroll
    for (int e = 0; e < 8; e++) {
        float v = acc[e];
#pragma unroll
        for (int off = 16; off; off >>= 1) v += __shfl_down_sync(0xffffffffu, v, off);
        if (lane == 0) s_red[e][wid] = v;
    }
    __syncthreads();
    if (tid < 8) {
        float s = 0.f;
#pragma unroll
        for (int w = 0; w < 8; w++) s += s_red[tid][w];
        s_l[tid] = s * s_g[tid];
    }
    __syncthreads();

    float4* o4 = (float4*)(out + (size_t)t * DIM);
    float4 v = o4[tid];
#pragma unroll
    for (int e = 0; e < 8; e++) {
        const float4* b4 = (const float4*)(out_b + (size_t)s_idx[e] * DIM);
        float4 bv = b4[tid];
        float l = s_l[e];
        v.x += l * bv.x; v.y += l * bv.y; v.z += l * bv.z; v.w += l * bv.w;
    }
    o4[tid] = v;
}

// ---------------------------------------------------------------------------
extern "C" void kernel_launch(void* const* d_in, const int* in_sizes, int n_in,
                              void* d_out, int out_size)
{
    const float* x     = (const float*)d_in[0];
    const float* Wq    = (const float*)d_in[1];
    const float* keys  = (const float*)d_in[2];
    const float* W_in  = (const float*)d_in[3];
    const float* W_out = (const float*)d_in[4];
    const float* in_a  = (const float*)d_in[5];
    const float* in_b  = (const float*)d_in[6];
    const float* out_a = (const float*)d_in[7];
    const float* out_b = (const float*)d_in[8];
    float* out = (float*)d_out;

    cudaFuncSetAttribute(gemm_sim_tc,
                         cudaFuncAttributeMaxDynamicSharedMemorySize, SIM_SMEM);

    // (1) cvt_x (2) cvt_Wi (3) mbuild->hi/lo (4) sim <- profiled slot
    cvt_x_k<<<TOKENS * DIM / 4 / 256, 256>>>(x);
    cvt_Wi_k<<<DINNER * DIM / 4 / 256, 256>>>(W_in);
    gemm_nn_mbuild<<<dim3(16, 1, 16), 256>>>(keys, Wq);
    gemm_sim_tc<<<dim3(16, TOKENS / 128), 256, SIM_SMEM>>>();

    gemm_hidden_tc<<<dim3(16, TOKENS / 128), 256>>>();
    combine_k<<<TOKENS * HEADS / 256, 256>>>();
    expert_in_k<<<TOKENS, 256>>>(x, in_a, in_b);

    cvt_Wo_k<<<DIM * DINNER / 4 / 256, 256>>>(W_out);
    gemm_out_tc<<<dim3(8, TOKENS / 128), 256>>>(out);
    expert_out_k<<<TOKENS, 256>>>(out_a, out_b, out);
}